// round 2
// baseline (speedup 1.0000x reference)
#include <cuda_runtime.h>
#include <math.h>
#include <stdint.h>

#define NIN     12
#define NC      16
#define HID     512
#define KBINS   8
#define BVAL    3.0f
#define LLAYERS 8
#define D_HALF  6
#define DIN     22      // D_HALF + NC
#define DOUT    138     // (3*K-1)*(NIN-D_HALF)
#define SPP     23      // 3*K-1 params per dim
#define TM      16      // rows per CTA
#define NT      256     // threads per CTA

__device__ __forceinline__ float eluf(float v) {
    return v > 0.0f ? v : expm1f(v);
}
__device__ __forceinline__ float softplusf(float v) {
    return v > 20.0f ? v : log1pf(expf(v));
}

// ---- packed f32x2 helpers ----
__device__ __forceinline__ uint64_t pk2(float a, float b) {
    uint64_t r;
    asm("mov.b64 %0, {%1, %2};" : "=l"(r) : "f"(a), "f"(b));
    return r;
}
__device__ __forceinline__ void fma2(uint64_t& d, uint64_t a, uint64_t b) {
    asm("fma.rn.f32x2 %0, %1, %2, %0;" : "+l"(d) : "l"(a), "l"(b));
}
__device__ __forceinline__ float upksum(uint64_t v) {
    float lo, hi;
    asm("mov.b64 {%0, %1}, %2;" : "=f"(lo), "=f"(hi) : "l"(v));
    return lo + hi;
}

// GEMM: h[TM][HID] @ W[HID][HID] + b -> elu -> h (in place).
// NT=256: jt = tid&127 -> 4 columns (4*jt..); rg = tid>>7 -> 8 rows.
// Packed f32x2 over k-parity: lane0 accumulates even k, lane1 odd k.
__device__ __forceinline__ void gemm_hid(const float* __restrict__ W,
                                         const float* __restrict__ bb,
                                         float (*h)[HID], int tid)
{
    const int jt = tid & 127;
    const int j0 = jt * 4;
    const int rb = (tid >> 7) * 8;

    uint64_t acc[8][4];
#pragma unroll
    for (int m = 0; m < 8; m++)
#pragma unroll
        for (int c = 0; c < 4; c++) acc[m][c] = 0ull;

    for (int k = 0; k < HID; k += 4) {
        const float* Wk = W + (size_t)k * HID + j0;
        float4 w0 = *(const float4*)(Wk);
        float4 w1 = *(const float4*)(Wk + HID);
        float4 w2 = *(const float4*)(Wk + 2 * HID);
        float4 w3 = *(const float4*)(Wk + 3 * HID);
        uint64_t p01[4], p23[4];
        p01[0] = pk2(w0.x, w1.x); p01[1] = pk2(w0.y, w1.y);
        p01[2] = pk2(w0.z, w1.z); p01[3] = pk2(w0.w, w1.w);
        p23[0] = pk2(w2.x, w3.x); p23[1] = pk2(w2.y, w3.y);
        p23[2] = pk2(w2.z, w3.z); p23[3] = pk2(w2.w, w3.w);
#pragma unroll
        for (int m = 0; m < 8; m++) {
            float4 hv = *(const float4*)&h[rb + m][k];
            uint64_t h01 = pk2(hv.x, hv.y);
            uint64_t h23 = pk2(hv.z, hv.w);
            fma2(acc[m][0], h01, p01[0]);
            fma2(acc[m][1], h01, p01[1]);
            fma2(acc[m][2], h01, p01[2]);
            fma2(acc[m][3], h01, p01[3]);
            fma2(acc[m][0], h23, p23[0]);
            fma2(acc[m][1], h23, p23[1]);
            fma2(acc[m][2], h23, p23[2]);
            fma2(acc[m][3], h23, p23[3]);
        }
    }
    float4 b4 = *(const float4*)(bb + j0);
    __syncthreads();   // all reads of h complete before in-place overwrite
#pragma unroll
    for (int m = 0; m < 8; m++) {
        float4 o;
        o.x = eluf(upksum(acc[m][0]) + b4.x);
        o.y = eluf(upksum(acc[m][1]) + b4.y);
        o.z = eluf(upksum(acc[m][2]) + b4.z);
        o.w = eluf(upksum(acc[m][3]) + b4.w);
        *(float4*)&h[rb + m][j0] = o;
    }
    __syncthreads();
}

__global__ __launch_bounds__(NT) void flow_kernel(
    const float* __restrict__ z,  const float* __restrict__ c,
    const float* __restrict__ W0, const float* __restrict__ b0,
    const float* __restrict__ W1, const float* __restrict__ b1,
    const float* __restrict__ W2, const float* __restrict__ b2,
    const float* __restrict__ W3, const float* __restrict__ b3,
    const int*   __restrict__ perms,
    float* __restrict__ out, int n)
{
    __shared__ float h_s[TM][HID];          // 32 KB activation buffer
    __shared__ float out_s[TM][DOUT + 2];   // spline params
    __shared__ float inp_s[TM][DIN];
    __shared__ float x_s[TM][NIN];
    __shared__ float xt_s[TM][NIN];
    __shared__ float c_s[TM][NC];
    __shared__ float ld_s[TM];
    __shared__ float lad_s[TM][D_HALF];
    __shared__ int   perm_s[(LLAYERS - 1) * NIN];

    const int tid  = threadIdx.x;
    const int row0 = blockIdx.x * TM;

    for (int i = tid; i < TM * NIN; i += NT) x_s[i / NIN][i % NIN] = z[(size_t)row0 * NIN + i];
    for (int i = tid; i < TM * NC;  i += NT) c_s[i / NC][i % NC]   = c[(size_t)row0 * NC + i];
    if (tid < TM) ld_s[tid] = 0.0f;
    if (tid < (LLAYERS - 1) * NIN) perm_s[tid] = perms[tid];
    __syncthreads();

    for (int layer = 0; layer < LLAYERS; layer++) {
        // ---- build inp = concat(x1, c) ----
        for (int i = tid; i < TM * DIN; i += NT) {
            int m = i / DIN, k = i % DIN;
            inp_s[m][k] = (k < D_HALF) ? x_s[m][k] : c_s[m][k - D_HALF];
        }
        __syncthreads();

        // ---- GEMM0: inp[TM][22] @ W0 -> elu -> h_s (small; scalar) ----
        {
            const float* W  = W0 + (size_t)layer * DIN * HID;
            const float* bb = b0 + (size_t)layer * HID;
            const int jt = tid & 127;
            const int j0 = jt * 4;
            const int rb = (tid >> 7) * 8;
            float a[8][4];
#pragma unroll
            for (int m = 0; m < 8; m++)
#pragma unroll
                for (int cc = 0; cc < 4; cc++) a[m][cc] = 0.0f;
            for (int k = 0; k < DIN; k++) {
                float4 w = *(const float4*)(W + (size_t)k * HID + j0);
#pragma unroll
                for (int m = 0; m < 8; m++) {
                    float hv = inp_s[rb + m][k];
                    a[m][0] = fmaf(hv, w.x, a[m][0]);
                    a[m][1] = fmaf(hv, w.y, a[m][1]);
                    a[m][2] = fmaf(hv, w.z, a[m][2]);
                    a[m][3] = fmaf(hv, w.w, a[m][3]);
                }
            }
            float4 b4 = *(const float4*)(bb + j0);
#pragma unroll
            for (int m = 0; m < 8; m++) {
                float4 o;
                o.x = eluf(a[m][0] + b4.x);
                o.y = eluf(a[m][1] + b4.y);
                o.z = eluf(a[m][2] + b4.z);
                o.w = eluf(a[m][3] + b4.w);
                *(float4*)&h_s[rb + m][j0] = o;
            }
            __syncthreads();
        }

        // ---- GEMM1, GEMM2: 512x512, packed f32x2, in-place ----
        gemm_hid(W1 + (size_t)layer * HID * HID, b1 + (size_t)layer * HID, h_s, tid);
        gemm_hid(W2 + (size_t)layer * HID * HID, b2 + (size_t)layer * HID, h_s, tid);

        // ---- GEMM3: h[TM][512] @ W3[512][138] + b3 -> out_s ----
        {
            const float* W  = W3 + (size_t)layer * HID * DOUT;
            const float* bb = b3 + (size_t)layer * DOUT;
            const int jl = tid & 127;
            const int rb = (tid >> 7) * 8;       // 2 groups of 8 rows
            const bool has2 = jl < (DOUT - 128); // 10 extra columns
            uint64_t a1[8], a2[8];
#pragma unroll
            for (int m = 0; m < 8; m++) { a1[m] = 0ull; a2[m] = 0ull; }
            for (int k = 0; k < HID; k += 4) {
                const float* Wk = W + (size_t)k * DOUT;
                float wa0 = Wk[jl];
                float wa1 = Wk[DOUT + jl];
                float wa2 = Wk[2 * DOUT + jl];
                float wa3 = Wk[3 * DOUT + jl];
                uint64_t pa01 = pk2(wa0, wa1), pa23 = pk2(wa2, wa3);
                uint64_t pb01 = 0, pb23 = 0;
                if (has2) {
                    float wb0 = Wk[128 + jl];
                    float wb1 = Wk[DOUT + 128 + jl];
                    float wb2 = Wk[2 * DOUT + 128 + jl];
                    float wb3 = Wk[3 * DOUT + 128 + jl];
                    pb01 = pk2(wb0, wb1); pb23 = pk2(wb2, wb3);
                }
#pragma unroll
                for (int m = 0; m < 8; m++) {
                    float4 hv = *(const float4*)&h_s[rb + m][k];
                    uint64_t h01 = pk2(hv.x, hv.y);
                    uint64_t h23 = pk2(hv.z, hv.w);
                    fma2(a1[m], h01, pa01);
                    fma2(a1[m], h23, pa23);
                    if (has2) {
                        fma2(a2[m], h01, pb01);
                        fma2(a2[m], h23, pb23);
                    }
                }
            }
            float bx  = bb[jl];
            float bx2 = has2 ? bb[128 + jl] : 0.0f;
#pragma unroll
            for (int m = 0; m < 8; m++) {
                out_s[rb + m][jl] = upksum(a1[m]) + bx;
                if (has2) out_s[rb + m][128 + jl] = upksum(a2[m]) + bx2;
            }
            __syncthreads();
        }

        // ---- RQ spline: one thread per (row, dim) ----
        if (tid < TM * D_HALF) {
            const int m = tid / D_HALF, d = tid % D_HALF;
            const float* p = &out_s[m][d * SPP];

            float e[KBINS];
            float mx = p[0];
#pragma unroll
            for (int i = 1; i < KBINS; i++) mx = fmaxf(mx, p[i]);
            float s = 0.0f;
#pragma unroll
            for (int i = 0; i < KBINS; i++) { e[i] = expf(p[i] - mx); s += e[i]; }
            float inv = 1.0f / s;
            float cw[KBINS + 1];
            cw[0] = -BVAL;
            {
                float run = 0.0f;
#pragma unroll
                for (int i = 0; i < KBINS - 1; i++) {
                    run += 0.001f + 0.992f * e[i] * inv;
                    cw[i + 1] = 2.0f * BVAL * run - BVAL;
                }
            }
            cw[KBINS] = BVAL;

            mx = p[KBINS];
#pragma unroll
            for (int i = 1; i < KBINS; i++) mx = fmaxf(mx, p[KBINS + i]);
            s = 0.0f;
#pragma unroll
            for (int i = 0; i < KBINS; i++) { e[i] = expf(p[KBINS + i] - mx); s += e[i]; }
            inv = 1.0f / s;
            float ch[KBINS + 1];
            ch[0] = -BVAL;
            {
                float run = 0.0f;
#pragma unroll
                for (int i = 0; i < KBINS - 1; i++) {
                    run += 0.001f + 0.992f * e[i] * inv;
                    ch[i + 1] = 2.0f * BVAL * run - BVAL;
                }
            }
            ch[KBINS] = BVAL;

            float dv[KBINS + 1];
            dv[0] = 1.0f; dv[KBINS] = 1.0f;
#pragma unroll
            for (int i = 1; i < KBINS; i++)
                dv[i] = 0.001f + softplusf(p[2 * KBINS + i - 1]);

            float x  = x_s[m][D_HALF + d];
            float xc = fminf(fmaxf(x, -BVAL), BVAL);
            int idx = 0;
#pragma unroll
            for (int i = 1; i < KBINS; i++) idx += (xc >= cw[i]) ? 1 : 0;

            float icw = cw[idx], iw = cw[idx + 1] - cw[idx];
            float ich = ch[idx], ih = ch[idx + 1] - ch[idx];
            float delta = ih / iw;
            float d0 = dv[idx], d1 = dv[idx + 1];
            float th  = (xc - icw) / iw;
            float t1m = th * (1.0f - th);
            float num = ih * (delta * th * th + d0 * t1m);
            float den = delta + (d0 + d1 - 2.0f * delta) * t1m;
            float o = ich + num / den;
            float omt = 1.0f - th;
            float dnum = delta * delta * (d1 * th * th + 2.0f * delta * t1m + d0 * omt * omt);
            float lad = logf(dnum) - 2.0f * logf(den);
            bool inside = (x >= -BVAL) && (x <= BVAL);
            x_s[m][D_HALF + d] = inside ? o : x;
            lad_s[m][d] = inside ? lad : 0.0f;
        }
        __syncthreads();

        if (tid < TM) {
            float acc = ld_s[tid];
#pragma unroll
            for (int d = 0; d < D_HALF; d++) acc += lad_s[tid][d];
            ld_s[tid] = acc;
        }

        // ---- permutation ----
        if (layer < LLAYERS - 1) {
            if (tid < TM * NIN) {
                int m = tid / NIN, j = tid % NIN;
                xt_s[m][j] = x_s[m][perm_s[layer * NIN + j]];
            }
            __syncthreads();
            if (tid < TM * NIN) {
                int m = tid / NIN, j = tid % NIN;
                x_s[m][j] = xt_s[m][j];
            }
        }
        __syncthreads();
    }

    // ---- write outputs: x [N,12] then total_ld [N] ----
    for (int i = tid; i < TM * NIN; i += NT)
        out[(size_t)row0 * NIN + i] = x_s[i / NIN][i % NIN];
    if (tid < TM)
        out[(size_t)n * NIN + row0 + tid] = ld_s[tid];
}

extern "C" void kernel_launch(void* const* d_in, const int* in_sizes, int n_in,
                              void* d_out, int out_size)
{
    const float* z     = (const float*)d_in[0];
    const float* c     = (const float*)d_in[1];
    const float* W0    = (const float*)d_in[2];
    const float* b0    = (const float*)d_in[3];
    const float* W1    = (const float*)d_in[4];
    const float* b1    = (const float*)d_in[5];
    const float* W2    = (const float*)d_in[6];
    const float* b2    = (const float*)d_in[7];
    const float* W3    = (const float*)d_in[8];
    const float* b3    = (const float*)d_in[9];
    const int*   perms = (const int*)d_in[10];

    int n = in_sizes[0] / NIN;
    int grid = (n + TM - 1) / TM;
    flow_kernel<<<grid, NT>>>(z, c, W0, b0, W1, b1, W2, b2, W3, b3, perms,
                              (float*)d_out, n);
}

// round 4
// speedup vs baseline: 1.3736x; 1.3736x over previous
#include <cuda_runtime.h>
#include <math.h>
#include <stdint.h>

#define NIN     12
#define NC      16
#define HID     512
#define KBINS   8
#define BVAL    3.0f
#define LLAYERS 8
#define D_HALF  6
#define DIN     22      // D_HALF + NC
#define DOUT    138     // (3*K-1)*(NIN-D_HALF)
#define SPP     23      // 3*K-1 params per dim
#define TM      16      // rows per CTA
#define NT      256     // threads per CTA
#define HPAD    20      // floats per h_t row (80B: 16B-aligned, pairs aligned)

__device__ __forceinline__ float eluf(float v) {
    return v > 0.0f ? v : expm1f(v);
}
__device__ __forceinline__ float softplusf(float v) {
    return v > 20.0f ? v : log1pf(expf(v));
}

// ---- packed f32x2 helpers ----
__device__ __forceinline__ uint64_t bc2(float a) {        // broadcast to both lanes
    uint64_t r;
    asm("mov.b64 %0, {%1, %1};" : "=l"(r) : "f"(a));
    return r;
}
__device__ __forceinline__ void fma2(uint64_t& d, uint64_t a, uint64_t b) {
    asm("fma.rn.f32x2 %0, %1, %2, %0;" : "+l"(d) : "l"(a), "l"(b));
}
__device__ __forceinline__ void upk(uint64_t v, float& lo, float& hi) {
    asm("mov.b64 {%0, %1}, %2;" : "=f"(lo), "=f"(hi) : "l"(v));
}

// GEMM: h_t (transposed act, [HID][TM]) @ W[HID][HID] + b -> elu -> h_t.
// jt=tid&127 -> 4 cols; rg=tid>>7 -> 8 rows = 4 row-pairs.
// acc[p][c] is f32x2 over row pair p, column j0+c.
__device__ __forceinline__ void gemm_hid_t(const float* __restrict__ W,
                                           const float* __restrict__ bb,
                                           float (*h_t)[HPAD], int tid)
{
    const int jt = tid & 127;
    const int j0 = jt * 4;
    const int rb = (tid >> 7) * 8;

    uint64_t acc[4][4];
#pragma unroll
    for (int p = 0; p < 4; p++)
#pragma unroll
        for (int c = 0; c < 4; c++) acc[p][c] = 0ull;

#pragma unroll 2
    for (int k = 0; k < HID; k++) {
        float4 w = *(const float4*)(W + (size_t)k * HID + j0);
        uint64_t wp0 = bc2(w.x), wp1 = bc2(w.y), wp2 = bc2(w.z), wp3 = bc2(w.w);
        ulonglong2 hA = *(const ulonglong2*)&h_t[k][rb];      // rows rb..rb+3
        ulonglong2 hB = *(const ulonglong2*)&h_t[k][rb + 4];  // rows rb+4..rb+7
        fma2(acc[0][0], hA.x, wp0); fma2(acc[0][1], hA.x, wp1);
        fma2(acc[0][2], hA.x, wp2); fma2(acc[0][3], hA.x, wp3);
        fma2(acc[1][0], hA.y, wp0); fma2(acc[1][1], hA.y, wp1);
        fma2(acc[1][2], hA.y, wp2); fma2(acc[1][3], hA.y, wp3);
        fma2(acc[2][0], hB.x, wp0); fma2(acc[2][1], hB.x, wp1);
        fma2(acc[2][2], hB.x, wp2); fma2(acc[2][3], hB.x, wp3);
        fma2(acc[3][0], hB.y, wp0); fma2(acc[3][1], hB.y, wp1);
        fma2(acc[3][2], hB.y, wp2); fma2(acc[3][3], hB.y, wp3);
    }

    float4 b4 = *(const float4*)(bb + j0);
    __syncthreads();   // all reads of h_t complete before overwrite
    float bv[4] = {b4.x, b4.y, b4.z, b4.w};
#pragma unroll
    for (int c = 0; c < 4; c++) {
        float v[8];
#pragma unroll
        for (int p = 0; p < 4; p++) upk(acc[p][c], v[2 * p], v[2 * p + 1]);
        float4 o0, o1;
        o0.x = eluf(v[0] + bv[c]); o0.y = eluf(v[1] + bv[c]);
        o0.z = eluf(v[2] + bv[c]); o0.w = eluf(v[3] + bv[c]);
        o1.x = eluf(v[4] + bv[c]); o1.y = eluf(v[5] + bv[c]);
        o1.z = eluf(v[6] + bv[c]); o1.w = eluf(v[7] + bv[c]);
        *(float4*)&h_t[j0 + c][rb]     = o0;
        *(float4*)&h_t[j0 + c][rb + 4] = o1;
    }
    __syncthreads();
}

__global__ __launch_bounds__(NT) void flow_kernel(
    const float* __restrict__ z,  const float* __restrict__ c,
    const float* __restrict__ W0, const float* __restrict__ b0,
    const float* __restrict__ W1, const float* __restrict__ b1,
    const float* __restrict__ W2, const float* __restrict__ b2,
    const float* __restrict__ W3, const float* __restrict__ b3,
    const int*   __restrict__ perms,
    float* __restrict__ out, int n)
{
    __shared__ float h_t[HID][HPAD];        // 40 KB transposed activations
    __shared__ float out_s[TM][DOUT + 2];   // spline params
    __shared__ float inp_t[DIN][TM];        // transposed MLP input
    __shared__ float x_s[TM][NIN];
    __shared__ float xt_s[TM][NIN];
    __shared__ float c_s[TM][NC];
    __shared__ float ld_s[TM];
    __shared__ float lad_s[TM][D_HALF];
    __shared__ int   perm_s[(LLAYERS - 1) * NIN];

    const int tid  = threadIdx.x;
    const int row0 = blockIdx.x * TM;

    for (int i = tid; i < TM * NIN; i += NT) x_s[i / NIN][i % NIN] = z[(size_t)row0 * NIN + i];
    for (int i = tid; i < TM * NC;  i += NT) c_s[i / NC][i % NC]   = c[(size_t)row0 * NC + i];
    if (tid < TM) ld_s[tid] = 0.0f;
    if (tid < (LLAYERS - 1) * NIN) perm_s[tid] = perms[tid];
    __syncthreads();

    for (int layer = 0; layer < LLAYERS; layer++) {
        // ---- build inp_t = concat(x1, c)^T  (DIN*TM = 352 > NT: must loop!) ----
        for (int i = tid; i < DIN * TM; i += NT) {
            int k = i / TM, m = i % TM;
            inp_t[k][m] = (k < D_HALF) ? x_s[m][k] : c_s[m][k - D_HALF];
        }
        __syncthreads();

        // ---- GEMM0: inp[TM][22] @ W0 -> elu -> h_t (small; scalar) ----
        {
            const float* W  = W0 + (size_t)layer * DIN * HID;
            const float* bb = b0 + (size_t)layer * HID;
            const int jt = tid & 127;
            const int j0 = jt * 4;
            const int rb = (tid >> 7) * 8;
            float a[8][4];
#pragma unroll
            for (int m = 0; m < 8; m++)
#pragma unroll
                for (int cc = 0; cc < 4; cc++) a[m][cc] = 0.0f;
            for (int k = 0; k < DIN; k++) {
                float4 w = *(const float4*)(W + (size_t)k * HID + j0);
#pragma unroll
                for (int m = 0; m < 8; m++) {
                    float hv = inp_t[k][rb + m];
                    a[m][0] = fmaf(hv, w.x, a[m][0]);
                    a[m][1] = fmaf(hv, w.y, a[m][1]);
                    a[m][2] = fmaf(hv, w.z, a[m][2]);
                    a[m][3] = fmaf(hv, w.w, a[m][3]);
                }
            }
            float4 b4 = *(const float4*)(bb + j0);
            float bv[4] = {b4.x, b4.y, b4.z, b4.w};
#pragma unroll
            for (int cc = 0; cc < 4; cc++) {
                float4 o0, o1;
                o0.x = eluf(a[0][cc] + bv[cc]); o0.y = eluf(a[1][cc] + bv[cc]);
                o0.z = eluf(a[2][cc] + bv[cc]); o0.w = eluf(a[3][cc] + bv[cc]);
                o1.x = eluf(a[4][cc] + bv[cc]); o1.y = eluf(a[5][cc] + bv[cc]);
                o1.z = eluf(a[6][cc] + bv[cc]); o1.w = eluf(a[7][cc] + bv[cc]);
                *(float4*)&h_t[j0 + cc][rb]     = o0;
                *(float4*)&h_t[j0 + cc][rb + 4] = o1;
            }
            __syncthreads();
        }

        // ---- GEMM1, GEMM2: 512x512, packed f32x2, transposed layout ----
        gemm_hid_t(W1 + (size_t)layer * HID * HID, b1 + (size_t)layer * HID, h_t, tid);
        gemm_hid_t(W2 + (size_t)layer * HID * HID, b2 + (size_t)layer * HID, h_t, tid);

        // ---- GEMM3: h[TM][512] @ W3[512][138] + b3 -> out_s ----
        {
            const float* W  = W3 + (size_t)layer * HID * DOUT;
            const float* bb = b3 + (size_t)layer * DOUT;
            const int jl = tid & 127;
            const int rb = (tid >> 7) * 8;       // 2 groups of 8 rows (4 pairs)
            const bool has2 = jl < (DOUT - 128); // 10 extra columns
            uint64_t a1[4], a2[4];
#pragma unroll
            for (int p = 0; p < 4; p++) { a1[p] = 0ull; a2[p] = 0ull; }
#pragma unroll 2
            for (int k = 0; k < HID; k++) {
                const float* Wk = W + (size_t)k * DOUT;
                uint64_t wp = bc2(Wk[jl]);
                ulonglong2 hA = *(const ulonglong2*)&h_t[k][rb];
                ulonglong2 hB = *(const ulonglong2*)&h_t[k][rb + 4];
                fma2(a1[0], hA.x, wp); fma2(a1[1], hA.y, wp);
                fma2(a1[2], hB.x, wp); fma2(a1[3], hB.y, wp);
                if (has2) {
                    uint64_t wp2 = bc2(Wk[128 + jl]);
                    fma2(a2[0], hA.x, wp2); fma2(a2[1], hA.y, wp2);
                    fma2(a2[2], hB.x, wp2); fma2(a2[3], hB.y, wp2);
                }
            }
            float bx  = bb[jl];
            float bx2 = has2 ? bb[128 + jl] : 0.0f;
#pragma unroll
            for (int p = 0; p < 4; p++) {
                float lo, hi;
                upk(a1[p], lo, hi);
                out_s[rb + 2 * p][jl]     = lo + bx;
                out_s[rb + 2 * p + 1][jl] = hi + bx;
                if (has2) {
                    upk(a2[p], lo, hi);
                    out_s[rb + 2 * p][128 + jl]     = lo + bx2;
                    out_s[rb + 2 * p + 1][128 + jl] = hi + bx2;
                }
            }
            __syncthreads();
        }

        // ---- RQ spline: one thread per (row, dim) ----
        if (tid < TM * D_HALF) {
            const int m = tid / D_HALF, d = tid % D_HALF;
            const float* p = &out_s[m][d * SPP];

            float e[KBINS];
            float mx = p[0];
#pragma unroll
            for (int i = 1; i < KBINS; i++) mx = fmaxf(mx, p[i]);
            float s = 0.0f;
#pragma unroll
            for (int i = 0; i < KBINS; i++) { e[i] = expf(p[i] - mx); s += e[i]; }
            float inv = 1.0f / s;
            float cw[KBINS + 1];
            cw[0] = -BVAL;
            {
                float run = 0.0f;
#pragma unroll
                for (int i = 0; i < KBINS - 1; i++) {
                    run += 0.001f + 0.992f * e[i] * inv;
                    cw[i + 1] = 2.0f * BVAL * run - BVAL;
                }
            }
            cw[KBINS] = BVAL;

            mx = p[KBINS];
#pragma unroll
            for (int i = 1; i < KBINS; i++) mx = fmaxf(mx, p[KBINS + i]);
            s = 0.0f;
#pragma unroll
            for (int i = 0; i < KBINS; i++) { e[i] = expf(p[KBINS + i] - mx); s += e[i]; }
            inv = 1.0f / s;
            float ch[KBINS + 1];
            ch[0] = -BVAL;
            {
                float run = 0.0f;
#pragma unroll
                for (int i = 0; i < KBINS - 1; i++) {
                    run += 0.001f + 0.992f * e[i] * inv;
                    ch[i + 1] = 2.0f * BVAL * run - BVAL;
                }
            }
            ch[KBINS] = BVAL;

            float dv[KBINS + 1];
            dv[0] = 1.0f; dv[KBINS] = 1.0f;
#pragma unroll
            for (int i = 1; i < KBINS; i++)
                dv[i] = 0.001f + softplusf(p[2 * KBINS + i - 1]);

            float x  = x_s[m][D_HALF + d];
            float xc = fminf(fmaxf(x, -BVAL), BVAL);
            int idx = 0;
#pragma unroll
            for (int i = 1; i < KBINS; i++) idx += (xc >= cw[i]) ? 1 : 0;

            float icw = cw[idx], iw = cw[idx + 1] - cw[idx];
            float ich = ch[idx], ih = ch[idx + 1] - ch[idx];
            float delta = ih / iw;
            float d0 = dv[idx], d1 = dv[idx + 1];
            float th  = (xc - icw) / iw;
            float t1m = th * (1.0f - th);
            float num = ih * (delta * th * th + d0 * t1m);
            float den = delta + (d0 + d1 - 2.0f * delta) * t1m;
            float o = ich + num / den;
            float omt = 1.0f - th;
            float dnum = delta * delta * (d1 * th * th + 2.0f * delta * t1m + d0 * omt * omt);
            float lad = logf(dnum) - 2.0f * logf(den);
            bool inside = (x >= -BVAL) && (x <= BVAL);
            x_s[m][D_HALF + d] = inside ? o : x;
            lad_s[m][d] = inside ? lad : 0.0f;
        }
        __syncthreads();

        if (tid < TM) {
            float acc = ld_s[tid];
#pragma unroll
            for (int d = 0; d < D_HALF; d++) acc += lad_s[tid][d];
            ld_s[tid] = acc;
        }

        // ---- permutation ----
        if (layer < LLAYERS - 1) {
            if (tid < TM * NIN) {
                int m = tid / NIN, j = tid % NIN;
                xt_s[m][j] = x_s[m][perm_s[layer * NIN + j]];
            }
            __syncthreads();
            if (tid < TM * NIN) {
                int m = tid / NIN, j = tid % NIN;
                x_s[m][j] = xt_s[m][j];
            }
        }
        __syncthreads();
    }

    // ---- write outputs: x [N,12] then total_ld [N] ----
    for (int i = tid; i < TM * NIN; i += NT)
        out[(size_t)row0 * NIN + i] = x_s[i / NIN][i % NIN];
    if (tid < TM)
        out[(size_t)n * NIN + row0 + tid] = ld_s[tid];
}

extern "C" void kernel_launch(void* const* d_in, const int* in_sizes, int n_in,
                              void* d_out, int out_size)
{
    const float* z     = (const float*)d_in[0];
    const float* c     = (const float*)d_in[1];
    const float* W0    = (const float*)d_in[2];
    const float* b0    = (const float*)d_in[3];
    const float* W1    = (const float*)d_in[4];
    const float* b1    = (const float*)d_in[5];
    const float* W2    = (const float*)d_in[6];
    const float* b2    = (const float*)d_in[7];
    const float* W3    = (const float*)d_in[8];
    const float* b3    = (const float*)d_in[9];
    const int*   perms = (const int*)d_in[10];

    int n = in_sizes[0] / NIN;
    int grid = (n + TM - 1) / TM;
    flow_kernel<<<grid, NT>>>(z, c, W0, b0, W1, b1, W2, b2, W3, b3, perms,
                              (float*)d_out, n);
}